// round 1
// baseline (speedup 1.0000x reference)
#include <cuda_runtime.h>
#include <math.h>

#define SEQ    2048
#define DM     1024
#define DH     64
#define NH     16
#define DFF    4096
#define NB     12
#define VOCAB  50257
#define LN_EPS 1e-5f

// ---------------- device scratch (no allocations allowed) ----------------
__device__ float g_x   [SEQ * DM];                 // activations [S, D]
__device__ float g_q   [SEQ * DM];                 // [H, S, dh]
__device__ float g_k   [SEQ * DM];                 // [H, S, dh]
__device__ float g_v   [SEQ * DM];                 // [H, S, dh]
__device__ float g_attn[(size_t)NH * SEQ * SEQ];   // [H, S, S] scores/probs (256 MB)
__device__ float g_mha [SEQ * DM];                 // concat heads [S, D]
__device__ float g_ff  [SEQ * DFF];                // ffn hidden [S, DFF]
__device__ float g_t2  [SEQ * DM];                 // pre-LN branch output [S, D]

// ---------------- embedding + sinusoidal PE ----------------
__global__ void embed_kernel(const int* __restrict__ tokens,
                             const float* __restrict__ emb)
{
    int s = blockIdx.x;
    int tok = tokens[s];
    const float* e = emb + (size_t)tok * DM;
    for (int d = threadIdx.x; d < DM; d += blockDim.x) {
        int iv = d & ~1;   // 2*floor(d/2)
        double ang = (double)s * pow(10000.0, -(double)iv / (double)DM);
        float pe = (d & 1) ? (float)cos(ang) : (float)sin(ang);
        g_x[s * DM + d] = e[d] + pe;
    }
}

// ---------------- generic tiled SGEMM: C = A @ B (+bias)(+relu) ----------------
// A: [M,K] lda ; B: [K,N] ldb ; C: [M,N] ldc. blockIdx.z adds per-z strides.
// CAUSAL: clip effective K to end of this row tile (attn rows are 0 beyond it).
// BM=BN=64, BK=16, 256 threads, 4x4 micro-tile per thread.
#define BM 64
#define BN 64
#define BK 16

template <bool RELU, bool CAUSAL>
__global__ void gemm_kernel(const float* __restrict__ A,
                            const float* __restrict__ B,
                            const float* __restrict__ bias,
                            float* __restrict__ C,
                            int M, int N, int K,
                            int lda, int ldb, int ldc,
                            long long sAz, long long sBz, long long sCz)
{
    A += (long long)blockIdx.z * sAz;
    B += (long long)blockIdx.z * sBz;
    C += (long long)blockIdx.z * sCz;

    const int m0 = blockIdx.y * BM;
    const int n0 = blockIdx.x * BN;

    int Keff = K;
    if (CAUSAL) { int km = m0 + BM; Keff = km < K ? km : K; }

    __shared__ float As[BK][BM];   // transposed: As[k][m]
    __shared__ float Bs[BK][BN];

    const int tid  = threadIdx.x;        // 0..255
    const int arow = tid >> 2;           // 0..63
    const int acol = (tid & 3) << 2;     // 0,4,8,12
    const int brow = tid >> 4;           // 0..15
    const int bcol = (tid & 15) << 2;    // 0..60
    const int tx   = tid & 15;
    const int ty   = tid >> 4;

    const bool bvec = ((ldb & 3) == 0);

    float acc[4][4] = {};

    for (int k0 = 0; k0 < Keff; k0 += BK) {
        // ---- load A tile (M,K multiples of 64/16 in all our launches) ----
        float4 av = *(const float4*)(A + (size_t)(m0 + arow) * lda + k0 + acol);
        As[acol + 0][arow] = av.x;
        As[acol + 1][arow] = av.y;
        As[acol + 2][arow] = av.z;
        As[acol + 3][arow] = av.w;

        // ---- load B tile (guard N edge; scalar path when ldb not 16B-friendly) ----
        float4 bv;
        const int bn = n0 + bcol;
        const float* Bp = B + (size_t)(k0 + brow) * ldb;
        if (bvec && (bn + 3) < N) {
            bv = *(const float4*)(Bp + bn);
        } else {
            bv.x = (bn + 0 < N) ? Bp[bn + 0] : 0.f;
            bv.y = (bn + 1 < N) ? Bp[bn + 1] : 0.f;
            bv.z = (bn + 2 < N) ? Bp[bn + 2] : 0.f;
            bv.w = (bn + 3 < N) ? Bp[bn + 3] : 0.f;
        }
        *(float4*)&Bs[brow][bcol] = bv;

        __syncthreads();

        #pragma unroll
        for (int k = 0; k < BK; ++k) {
            float4 a4 = *(const float4*)&As[k][ty * 4];
            float4 b4 = *(const float4*)&Bs[k][tx * 4];
            float a[4] = {a4.x, a4.y, a4.z, a4.w};
            float b[4] = {b4.x, b4.y, b4.z, b4.w};
            #pragma unroll
            for (int i = 0; i < 4; ++i)
                #pragma unroll
                for (int j = 0; j < 4; ++j)
                    acc[i][j] = fmaf(a[i], b[j], acc[i][j]);
        }
        __syncthreads();
    }

    // ---- epilogue ----
    #pragma unroll
    for (int i = 0; i < 4; ++i) {
        const int m = m0 + ty * 4 + i;
        float* Crow = C + (size_t)m * ldc;
        #pragma unroll
        for (int j = 0; j < 4; ++j) {
            const int n = n0 + tx * 4 + j;
            if (n < N) {
                float v = acc[i][j];
                if (bias) v += bias[n];
                if (RELU) v = fmaxf(v, 0.f);
                Crow[n] = v;
            }
        }
    }
}

// ---------------- attention scores: attn[h,s,t] = (Q_h[s]·K_h[t]) / 8 ----------------
// Skips tiles fully above the diagonal (softmax zero-fills them).
__global__ void scores_kernel(const float* __restrict__ Q,
                              const float* __restrict__ Km)
{
    const int h  = blockIdx.z;
    const int s0 = blockIdx.y * 64;
    const int t0 = blockIdx.x * 64;
    if (t0 > s0 + 63) return;   // fully masked tile

    const float* Qh = Q  + (size_t)h * SEQ * DH;
    const float* Kh = Km + (size_t)h * SEQ * DH;

    __shared__ float Qs[64][DH + 1];
    __shared__ float Ks[64][DH + 1];

    const int tid = threadIdx.x;
    #pragma unroll
    for (int r = 0; r < 4; ++r) {
        int idx = tid + r * 256;       // 0..1023
        int row = idx >> 4;            // 0..63
        int c4  = (idx & 15) << 2;     // 0..60
        float4 qv = *(const float4*)(Qh + (size_t)(s0 + row) * DH + c4);
        Qs[row][c4 + 0] = qv.x; Qs[row][c4 + 1] = qv.y;
        Qs[row][c4 + 2] = qv.z; Qs[row][c4 + 3] = qv.w;
        float4 kv = *(const float4*)(Kh + (size_t)(t0 + row) * DH + c4);
        Ks[row][c4 + 0] = kv.x; Ks[row][c4 + 1] = kv.y;
        Ks[row][c4 + 2] = kv.z; Ks[row][c4 + 3] = kv.w;
    }
    __syncthreads();

    const int tx = tid & 15, ty = tid >> 4;
    float acc[4][4] = {};
    #pragma unroll 8
    for (int k = 0; k < DH; ++k) {
        float a[4], b[4];
        #pragma unroll
        for (int i = 0; i < 4; ++i) a[i] = Qs[ty * 4 + i][k];
        #pragma unroll
        for (int j = 0; j < 4; ++j) b[j] = Ks[tx * 4 + j][k];
        #pragma unroll
        for (int i = 0; i < 4; ++i)
            #pragma unroll
            for (int j = 0; j < 4; ++j)
                acc[i][j] = fmaf(a[i], b[j], acc[i][j]);
    }

    const float scale = 0.125f;   // 1/sqrt(64)
    #pragma unroll
    for (int i = 0; i < 4; ++i) {
        const int s = s0 + ty * 4 + i;
        float* row = g_attn + ((size_t)h * SEQ + s) * SEQ;
        #pragma unroll
        for (int j = 0; j < 4; ++j)
            row[t0 + tx * 4 + j] = acc[i][j] * scale;
    }
}

// ---------------- causal row softmax (in place, zero-fills t > s) ----------------
__global__ void softmax_kernel()
{
    const int s = blockIdx.x, h = blockIdx.y, tid = threadIdx.x;
    float* row = g_attn + ((size_t)h * SEQ + s) * SEQ;
    const int len = s + 1;

    __shared__ float red[256];

    float m = -1e30f;
    for (int t = tid; t < len; t += 256) m = fmaxf(m, row[t]);
    red[tid] = m; __syncthreads();
    for (int st = 128; st; st >>= 1) { if (tid < st) red[tid] = fmaxf(red[tid], red[tid + st]); __syncthreads(); }
    m = red[0]; __syncthreads();

    float sum = 0.f;
    for (int t = tid; t < len; t += 256) { float e = __expf(row[t] - m); row[t] = e; sum += e; }
    red[tid] = sum; __syncthreads();
    for (int st = 128; st; st >>= 1) { if (tid < st) red[tid] += red[tid + st]; __syncthreads(); }
    const float inv = 1.0f / red[0];

    for (int t = tid; t < len; t += 256) row[t] *= inv;
    for (int t = len + tid; t < SEQ; t += 256) row[t] = 0.f;   // zero masked tail
}

// ---------------- fused residual + LayerNorm: x = LN(x + branch)*g + b ----------------
__global__ void ln_kernel(const float* __restrict__ branch,
                          const float* __restrict__ g,
                          const float* __restrict__ b)
{
    const int s = blockIdx.x, tid = threadIdx.x;
    __shared__ float red[256];

    float v[4];
    float sum = 0.f;
    #pragma unroll
    for (int r = 0; r < 4; ++r) {
        int d = tid + r * 256;
        v[r] = g_x[s * DM + d] + branch[s * DM + d];
        sum += v[r];
    }
    red[tid] = sum; __syncthreads();
    for (int st = 128; st; st >>= 1) { if (tid < st) red[tid] += red[tid + st]; __syncthreads(); }
    const float mu = red[0] * (1.0f / DM);
    __syncthreads();

    float sq = 0.f;
    #pragma unroll
    for (int r = 0; r < 4; ++r) { float d0 = v[r] - mu; sq += d0 * d0; }
    red[tid] = sq; __syncthreads();
    for (int st = 128; st; st >>= 1) { if (tid < st) red[tid] += red[tid + st]; __syncthreads(); }
    const float rstd = rsqrtf(red[0] * (1.0f / DM) + LN_EPS);

    #pragma unroll
    for (int r = 0; r < 4; ++r) {
        int d = tid + r * 256;
        g_x[s * DM + d] = (v[r] - mu) * rstd * g[d] + b[d];
    }
}

// ---------------- host launch ----------------
extern "C" void kernel_launch(void* const* d_in, const int* in_sizes, int n_in,
                              void* d_out, int out_size)
{
    const int*   tokens = (const int*)  d_in[0];
    const float* emb    = (const float*)d_in[1];
    const float* Wq     = (const float*)d_in[2];
    const float* Wk     = (const float*)d_in[3];
    const float* Wv     = (const float*)d_in[4];
    const float* Wo     = (const float*)d_in[5];
    const float* bo     = (const float*)d_in[6];
    const float* ln1g   = (const float*)d_in[7];
    const float* ln1b   = (const float*)d_in[8];
    const float* W1     = (const float*)d_in[9];
    const float* b1     = (const float*)d_in[10];
    const float* W2     = (const float*)d_in[11];
    const float* b2     = (const float*)d_in[12];
    const float* ln2g   = (const float*)d_in[13];
    const float* ln2b   = (const float*)d_in[14];
    const float* Wout   = (const float*)d_in[15];
    const float* bout   = (const float*)d_in[16];
    float* out = (float*)d_out;

    float *x, *q, *k, *v, *attn, *mha, *ff, *t2;
    cudaGetSymbolAddress((void**)&x,    g_x);
    cudaGetSymbolAddress((void**)&q,    g_q);
    cudaGetSymbolAddress((void**)&k,    g_k);
    cudaGetSymbolAddress((void**)&v,    g_v);
    cudaGetSymbolAddress((void**)&attn, g_attn);
    cudaGetSymbolAddress((void**)&mha,  g_mha);
    cudaGetSymbolAddress((void**)&ff,   g_ff);
    cudaGetSymbolAddress((void**)&t2,   g_t2);

    embed_kernel<<<SEQ, 256>>>(tokens, emb);

    const dim3 blk(256);
    for (int l = 0; l < NB; ++l) {
        const float* Wql = Wq + (size_t)l * NH * DM * DH;
        const float* Wkl = Wk + (size_t)l * NH * DM * DH;
        const float* Wvl = Wv + (size_t)l * NH * DM * DH;

        // Q/K/V projections: per-head GEMM via blockIdx.z
        gemm_kernel<false, false><<<dim3(1, SEQ / 64, NH), blk>>>(
            x, Wql, nullptr, q, SEQ, DH, DM, DM, DH, DH,
            0LL, (long long)DM * DH, (long long)SEQ * DH);
        gemm_kernel<false, false><<<dim3(1, SEQ / 64, NH), blk>>>(
            x, Wkl, nullptr, k, SEQ, DH, DM, DM, DH, DH,
            0LL, (long long)DM * DH, (long long)SEQ * DH);
        gemm_kernel<false, false><<<dim3(1, SEQ / 64, NH), blk>>>(
            x, Wvl, nullptr, v, SEQ, DH, DM, DM, DH, DH,
            0LL, (long long)DM * DH, (long long)SEQ * DH);

        // scores (causal tile-skip) + softmax
        scores_kernel<<<dim3(SEQ / 64, SEQ / 64, NH), blk>>>(q, k);
        softmax_kernel<<<dim3(SEQ, NH), blk>>>();

        // heads = attn @ V, written in concat layout [S, H*dh]; K clipped causally
        gemm_kernel<false, true><<<dim3(1, SEQ / 64, NH), blk>>>(
            attn, v, nullptr, mha, SEQ, DH, SEQ, SEQ, DH, DM,
            (long long)SEQ * SEQ, (long long)SEQ * DH, (long long)DH);

        // output projection + residual LN
        gemm_kernel<false, false><<<dim3(DM / 64, SEQ / 64, 1), blk>>>(
            mha, Wo + (size_t)l * DM * DM, bo + (size_t)l * DM, t2,
            SEQ, DM, DM, DM, DM, DM, 0LL, 0LL, 0LL);
        ln_kernel<<<SEQ, blk>>>(t2, ln1g + (size_t)l * DM, ln1b + (size_t)l * DM);

        // FFN
        gemm_kernel<true, false><<<dim3(DFF / 64, SEQ / 64, 1), blk>>>(
            x, W1 + (size_t)l * DM * DFF, b1 + (size_t)l * DFF, ff,
            SEQ, DFF, DM, DM, DFF, DFF, 0LL, 0LL, 0LL);
        gemm_kernel<false, false><<<dim3(DM / 64, SEQ / 64, 1), blk>>>(
            ff, W2 + (size_t)l * DFF * DM, b2 + (size_t)l * DM, t2,
            SEQ, DM, DFF, DFF, DM, DM, 0LL, 0LL, 0LL);
        ln_kernel<<<SEQ, blk>>>(t2, ln2g + (size_t)l * DM, ln2b + (size_t)l * DM);
    }

    // final logits: [S, VOCAB]
    gemm_kernel<false, false><<<dim3((VOCAB + 63) / 64, SEQ / 64, 1), blk>>>(
        x, Wout, bout, out, SEQ, VOCAB, DM, DM, VOCAB, VOCAB, 0LL, 0LL, 0LL);
}